// round 17
// baseline (speedup 1.0000x reference)
#include <cuda_runtime.h>

// Problem constants (fixed by the reference)
#define T_TOTAL   262144
#define S_DIM     512
#define K_ROWS    258       // NUM_KNOTS + DEGREE - 1
#define NKNOTS    262       // NUM_KNOTS + 2*DEGREE
#define DEG       3

#define TIMES_PER_CHUNK 64
#define TOTAL_CHUNKS (T_TOTAL / TIMES_PER_CHUNK)   // 4096

// Scratch for weight row sums (allocation-free per harness rules)
__device__ float g_rowsum[K_ROWS];

// ---------------------------------------------------------------------------
// Kernel 1: rowsum[r] = sum_s W[r, s]. 258 blocks x 128 threads,
// one float4 per thread (single LDG.128) -> warp reduce -> smem reduce.
// ---------------------------------------------------------------------------
__global__ void rowsum_kernel(const float* __restrict__ weights) {
    const int row = blockIdx.x;
    const float4 v = __ldg((const float4*)(weights + row * S_DIM) + threadIdx.x);
    float s = v.x + v.y + v.z + v.w;
    #pragma unroll
    for (int o = 16; o > 0; o >>= 1)
        s += __shfl_down_sync(0xffffffffu, s, o);
    __shared__ float ws[4];
    if ((threadIdx.x & 31) == 0) ws[threadIdx.x >> 5] = s;
    __syncthreads();
    if (threadIdx.x == 0)
        g_rowsum[row] = ws[0] + ws[1] + ws[2] + ws[3];
}

// ---------------------------------------------------------------------------
// Kernel 2: PERSISTENT fused kernel. Grid = exact resident capacity.
// Each block owns a contiguous balanced range of 64-time chunks (imbalance
// <= 1 chunk), eliminating the 0.22-wave quantization tail of the 4096-block
// launch. Per chunk, identical to the proven R16 structure:
//   Phase B: threads 0..63 search + de Boor -> coeffs/base in smem.
//   Phase C: register weight-cache + fast path when the whole chunk shares
//            one span; contiguous chunks usually share the span, so priming
//            is skipped across chunks too (curBase carried in registers).
// NOTE: natural register allocation — forcing 32 regs spills the weight
// cache (R10); splitting coeffs to gmem costs more than it saves (R14).
// ---------------------------------------------------------------------------
__global__ __launch_bounds__(512)
void bspline_kernel(const float* __restrict__ times,
                    const float* __restrict__ weights,
                    const float* __restrict__ knots,
                    float* __restrict__ out)
{
    __shared__ float  s_knots[NKNOTS];
    __shared__ float4 s_c[TIMES_PER_CHUNK];
    __shared__ int    s_base[TIMES_PER_CHUNK];

    const int tid = threadIdx.x;

    // Stage knots once per block
    if (tid < NKNOTS) s_knots[tid] = knots[tid];

    // Balanced contiguous chunk range for this block
    const int nb = gridDim.x, b = blockIdx.x;
    const int q  = TOTAL_CHUNKS / nb, r = TOTAL_CHUNKS % nb;
    const int c_begin = b * q + (b < r ? b : r);
    const int c_end   = c_begin + q + (b < r ? 1 : 0);

    // Phase-C lane decomposition (loop-invariant)
    const int tl   = tid >> 7;    // 0..3: time sub-slot (warp-uniform)
    const int lane = tid & 127;   // column group
    const int col  = lane << 2;   // 4 columns per thread

    int curBase = -1;             // weight-cache tag, carried across chunks
    float4 w0, w1, w2, w3;

    for (int ci = c_begin; ci < c_end; ++ci) {
        const int t0 = ci * TIMES_PER_CHUNK;

        __syncthreads();   // smem (s_c/s_base) safe to overwrite

        // Phase B: 64 parallel coefficient computations
        if (tid < TIMES_PER_CHUNK) {
            const float t = times[t0 + tid];
            float c0 = 0.f, c1 = 0.f, c2 = 0.f, c3 = 0.f, sum = 0.f;
            int base = 0;

            // Valid half-open span exists only if t < knots[258] (= t_max).
            // t == t_max => reference basis row is all zeros.
            if (t < s_knots[NKNOTS - DEG - 1]) {
                // binary search: largest i in [3, 257] with knots[i] <= t
                int lo = DEG, hi = NKNOTS - DEG - 2;   // 3 .. 257
                while (lo < hi) {
                    const int mid = (lo + hi + 1) >> 1;
                    if (s_knots[mid] <= t) lo = mid; else hi = mid - 1;
                }
                const int i = lo;  // knots[i] <= t < knots[i+1], non-empty

                // Local de Boor triangle (denominators > 0 in a valid span;
                // algebraically identical to the reference recursion).
                float Nv[DEG + 1], left[DEG + 1], right[DEG + 1];
                Nv[0] = 1.0f;
                #pragma unroll
                for (int j = 1; j <= DEG; j++) {
                    left[j]  = t - s_knots[i + 1 - j];
                    right[j] = s_knots[i + j] - t;
                    float saved = 0.0f;
                    #pragma unroll
                    for (int rr = 0; rr < j; rr++) {
                        const float temp = Nv[rr] / (right[rr + 1] + left[j - rr]);
                        Nv[rr] = saved + right[rr + 1] * temp;
                        saved = left[j - rr] * temp;
                    }
                    Nv[j] = saved;
                }
                base = i - DEG;
                c0 = Nv[0]; c1 = Nv[1]; c2 = Nv[2]; c3 = Nv[3];
                sum = c0 * g_rowsum[base]     + c1 * g_rowsum[base + 1]
                    + c2 * g_rowsum[base + 2] + c3 * g_rowsum[base + 3];
            }

            s_c[tid]    = make_float4(c0, c1, c2, c3);
            s_base[tid] = base;
            // b_splines_sum lives after the T*S b_splines block
            out[(size_t)T_TOTAL * S_DIM + (t0 + tid)] = sum;
        }
        __syncthreads();

        // Phase C: streaming combine + store
        float* out_ptr = out + (size_t)(t0 + tl) * S_DIM + col;
        const int firstBase = s_base[0];

        if (firstBase == s_base[TIMES_PER_CHUNK - 1]) {
            // Fast path (~94%+ of chunks): single span for the whole chunk.
            if (firstBase != curBase) {            // usually false across chunks
                curBase = firstBase;
                const float* wq = weights + (size_t)firstBase * S_DIM + col;
                w0 = __ldg((const float4*)(wq));
                w1 = __ldg((const float4*)(wq + S_DIM));
                w2 = __ldg((const float4*)(wq + 2 * S_DIM));
                w3 = __ldg((const float4*)(wq + 3 * S_DIM));
            }
            #pragma unroll 4
            for (int it = 0; it < TIMES_PER_CHUNK / 4; ++it) {
                const float4 c = s_c[(it << 2) + tl];
                float4 o;
                o.x = c.x * w0.x + c.y * w1.x + c.z * w2.x + c.w * w3.x;
                o.y = c.x * w0.y + c.y * w1.y + c.z * w2.y + c.w * w3.y;
                o.z = c.x * w0.z + c.y * w1.z + c.z * w2.z + c.w * w3.z;
                o.w = c.x * w0.w + c.y * w1.w + c.z * w2.w + c.w * w3.w;
                __stcs((float4*)out_ptr, o);   // streaming: no L2 pollution
                out_ptr += 4 * S_DIM;
            }
        } else {
            // Slow path: span changes inside the chunk (warp-uniform check).
            #pragma unroll 2
            for (int it = 0; it < TIMES_PER_CHUNK / 4; ++it) {
                const int slot = (it << 2) + tl;
                const int base = s_base[slot];
                if (base != curBase) {
                    curBase = base;
                    const float* wq = weights + (size_t)base * S_DIM + col;
                    w0 = __ldg((const float4*)(wq));
                    w1 = __ldg((const float4*)(wq + S_DIM));
                    w2 = __ldg((const float4*)(wq + 2 * S_DIM));
                    w3 = __ldg((const float4*)(wq + 3 * S_DIM));
                }
                const float4 c = s_c[slot];
                float4 o;
                o.x = c.x * w0.x + c.y * w1.x + c.z * w2.x + c.w * w3.x;
                o.y = c.x * w0.y + c.y * w1.y + c.z * w2.y + c.w * w3.y;
                o.z = c.x * w0.z + c.y * w1.z + c.z * w2.z + c.w * w3.z;
                o.w = c.x * w0.w + c.y * w1.w + c.z * w2.w + c.w * w3.w;
                __stcs((float4*)out_ptr, o);
                out_ptr += 4 * S_DIM;
            }
        }
    }
}

// ---------------------------------------------------------------------------
// Launch: inputs are (times, weights, knots) per metadata order.
// Output buffer: [ b_splines (T*S floats) | b_splines_sum (T floats) ].
// ---------------------------------------------------------------------------
extern "C" void kernel_launch(void* const* d_in, const int* in_sizes, int n_in,
                              void* d_out, int out_size) {
    const float* times   = (const float*)d_in[0];
    const float* weights = (const float*)d_in[1];
    const float* knots   = (const float*)d_in[2];
    float* out = (float*)d_out;

    // Persistent grid = exact resident capacity (deterministic per device).
    static int grid_b = 0;
    if (grid_b == 0) {
        int dev = 0, nsm = 0, occ = 0;
        cudaGetDevice(&dev);
        cudaDeviceGetAttribute(&nsm, cudaDevAttrMultiProcessorCount, dev);
        cudaOccupancyMaxActiveBlocksPerMultiprocessor(&occ, bspline_kernel, 512, 0);
        if (occ < 1) occ = 1;
        grid_b = nsm * occ;
        if (grid_b < 1) grid_b = 444;
        if (grid_b > TOTAL_CHUNKS) grid_b = TOTAL_CHUNKS;
    }

    rowsum_kernel<<<K_ROWS, 128>>>(weights);
    bspline_kernel<<<grid_b, 512>>>(times, weights, knots, out);
}